// round 2
// baseline (speedup 1.0000x reference)
#include <cuda_runtime.h>
#include <cstdint>

#define NN 50000
#define EE 1000000
#define DD 64

// ---------------- scratch (device globals; no allocation allowed) ----------------
__device__ float g_agg[NN * DD];     // segment_sum(edge_feat) per node
__device__ float g_trans[NN * 3];    // segment_sum(trans) per node
__device__ float g_cnt[NN];          // edge count per node

// ---------------- zero scratch ----------------
__global__ void zero_kernel() {
    int i = blockIdx.x * blockDim.x + threadIdx.x;
    int stride = gridDim.x * blockDim.x;
    for (int j = i; j < NN * DD; j += stride) g_agg[j] = 0.f;
    for (int j = i; j < NN * 3;  j += stride) g_trans[j] = 0.f;
    for (int j = i; j < NN;      j += stride) g_cnt[j] = 0.f;
}

// ---------------- edge kernel ----------------
// Layout: lane = edge. Each warp processes 32 edges/iteration.
// Inputs staged transposed in SMEM: stage[k*33 + lane] (stride 33 -> conflict-free
// both for the transposing writes and the per-lane column reads).
// Weights in SMEM, broadcast via LDS.128 (1 LDS per 4 FFMA).
//
// SMEM float map:
//   [0,8256)      We1 (129x64)
//   [8256,8320)   be1
//   [8320,12416)  We2 (64x64)
//   [12416,12480) be2
//   [12480,16576) Wc1 (64x64)
//   [16576,16640) bc1
//   [16640,16704) Wc2 (64)
//   [16704, +8*4260)  per-warp stage buffers (129 rows x 33 cols, padded to 4260)
//   [50784, +8*64)    per-warp index buffers (32 rows + 32 cols)
#define EDGE_STAGE_BASE 16704
#define EDGE_STAGE_STRIDE 4260
#define EDGE_IDX_BASE (EDGE_STAGE_BASE + 8 * EDGE_STAGE_STRIDE)   // 50784
#define EDGE_SMEM_FLOATS (EDGE_IDX_BASE + 8 * 64)                 // 51296
#define EDGE_SMEM_BYTES (EDGE_SMEM_FLOATS * 4)                    // 205184

__global__ void __launch_bounds__(256, 1) edge_kernel(
    const float* __restrict__ h, const float* __restrict__ coord,
    const int* __restrict__ ei,
    const float* __restrict__ We1, const float* __restrict__ be1,
    const float* __restrict__ We2, const float* __restrict__ be2,
    const float* __restrict__ Wc1, const float* __restrict__ bc1,
    const float* __restrict__ Wc2)
{
    extern __shared__ float s[];
    const int tid = threadIdx.x;

    // load weights to smem
    for (int i = tid; i < 8256; i += 256) s[i]          = We1[i];
    for (int i = tid; i < 64;   i += 256) s[8256 + i]   = be1[i];
    for (int i = tid; i < 4096; i += 256) s[8320 + i]   = We2[i];
    for (int i = tid; i < 64;   i += 256) s[12416 + i]  = be2[i];
    for (int i = tid; i < 4096; i += 256) s[12480 + i]  = Wc1[i];
    for (int i = tid; i < 64;   i += 256) s[16576 + i]  = bc1[i];
    for (int i = tid; i < 64;   i += 256) s[16640 + i]  = Wc2[i];
    __syncthreads();

    const int warp = tid >> 5, lane = tid & 31;
    float* stage = s + EDGE_STAGE_BASE + warp * EDGE_STAGE_STRIDE;
    int*   iidx  = (int*)(s + EDGE_IDX_BASE + warp * 64);

    const int gw = blockIdx.x * 8 + warp;
    const int nwarps = gridDim.x * 8;
    const int niter = EE / 32;   // 31250 exactly

    for (int it = gw; it < niter; it += nwarps) {
        const int e = it * 32 + lane;
        const int row = ei[e];
        const int col = ei[EE + e];
        iidx[lane] = row;
        iidx[32 + lane] = col;

        const float dx = coord[row * 3 + 0] - coord[col * 3 + 0];
        const float dy = coord[row * 3 + 1] - coord[col * 3 + 1];
        const float dz = coord[row * 3 + 2] - coord[col * 3 + 2];
        const float radial = dx * dx + dy * dy + dz * dz;
        stage[128 * 33 + lane] = radial;
        __syncwarp();

        // gather h[row], h[col] -> transposed stage rows 0..127
        #pragma unroll 4
        for (int r = 0; r < 32; r++) {
            const int rr = iidx[r];
            const int cc = iidx[32 + r];
            const float* hr = h + (size_t)rr * 64;
            const float* hc = h + (size_t)cc * 64;
            stage[(lane)      * 33 + r] = hr[lane];
            stage[(lane + 32) * 33 + r] = hr[lane + 32];
            stage[(lane + 64) * 33 + r] = hc[lane];
            stage[(lane + 96) * 33 + r] = hc[lane + 32];
        }
        __syncwarp();

        // ---- layer 1: m = relu(e_in @ We1 + be1) ----
        float acc[64];
        #pragma unroll
        for (int t = 0; t < 64; t += 4) {
            float4 b = *(const float4*)(s + 8256 + t);
            acc[t] = b.x; acc[t + 1] = b.y; acc[t + 2] = b.z; acc[t + 3] = b.w;
        }
        for (int k = 0; k < 129; k++) {
            const float x = stage[k * 33 + lane];
            const float4* w = (const float4*)(s + k * 64);
            #pragma unroll
            for (int t = 0; t < 16; t++) {
                float4 wv = w[t];
                acc[4 * t + 0] += x * wv.x;
                acc[4 * t + 1] += x * wv.y;
                acc[4 * t + 2] += x * wv.z;
                acc[4 * t + 3] += x * wv.w;
            }
        }
        #pragma unroll
        for (int t = 0; t < 64; t++) stage[t * 33 + lane] = fmaxf(acc[t], 0.f);

        // ---- layer 2: ef = relu(m @ We2 + be2) ----
        #pragma unroll
        for (int t = 0; t < 64; t += 4) {
            float4 b = *(const float4*)(s + 12416 + t);
            acc[t] = b.x; acc[t + 1] = b.y; acc[t + 2] = b.z; acc[t + 3] = b.w;
        }
        for (int k = 0; k < 64; k++) {
            const float x = stage[k * 33 + lane];
            const float4* w = (const float4*)(s + 8320 + k * 64);
            #pragma unroll
            for (int t = 0; t < 16; t++) {
                float4 wv = w[t];
                acc[4 * t + 0] += x * wv.x;
                acc[4 * t + 1] += x * wv.y;
                acc[4 * t + 2] += x * wv.z;
                acc[4 * t + 3] += x * wv.w;
            }
        }
        #pragma unroll
        for (int t = 0; t < 64; t++) {
            acc[t] = fmaxf(acc[t], 0.f);
            stage[t * 33 + lane] = acc[t];
        }

        // scatter edge_feat into g_agg now (frees acc for layer 3)
        {
            float* dst = g_agg + (size_t)row * 64;
            #pragma unroll
            for (int t = 0; t < 64; t++) atomicAdd(dst + t, acc[t]);
        }

        // ---- layer 3: c = relu(ef @ Wc1 + bc1); gate = c . Wc2 ----
        #pragma unroll
        for (int t = 0; t < 64; t += 4) {
            float4 b = *(const float4*)(s + 16576 + t);
            acc[t] = b.x; acc[t + 1] = b.y; acc[t + 2] = b.z; acc[t + 3] = b.w;
        }
        for (int k = 0; k < 64; k++) {
            const float x = stage[k * 33 + lane];
            const float4* w = (const float4*)(s + 12480 + k * 64);
            #pragma unroll
            for (int t = 0; t < 16; t++) {
                float4 wv = w[t];
                acc[4 * t + 0] += x * wv.x;
                acc[4 * t + 1] += x * wv.y;
                acc[4 * t + 2] += x * wv.z;
                acc[4 * t + 3] += x * wv.w;
            }
        }
        float gate = 0.f;
        #pragma unroll
        for (int t = 0; t < 64; t++) gate += fmaxf(acc[t], 0.f) * s[16640 + t];

        const float tx = fminf(fmaxf(dx * gate, -100.f), 100.f);
        const float ty = fminf(fmaxf(dy * gate, -100.f), 100.f);
        const float tz = fminf(fmaxf(dz * gate, -100.f), 100.f);
        atomicAdd(&g_trans[row * 3 + 0], tx);
        atomicAdd(&g_trans[row * 3 + 1], ty);
        atomicAdd(&g_trans[row * 3 + 2], tz);
        atomicAdd(&g_cnt[row], 1.f);
        __syncwarp();
    }
}

// ---------------- node kernel ----------------
// lane = node. stage: rows 0..63 = h, rows 64..127 = agg (hidden overwrites 64..127).
// SMEM: [0,8192) Wn1, [8192,8256) bn1, [8256,12352) Wn2, [12352,12416) bn2,
//       [12416, +8*4224) per-warp stages.
#define NODE_STAGE_BASE 12416
#define NODE_STAGE_STRIDE 4224
#define NODE_SMEM_FLOATS (NODE_STAGE_BASE + 8 * NODE_STAGE_STRIDE)  // 46208
#define NODE_SMEM_BYTES (NODE_SMEM_FLOATS * 4)                      // 184832

__global__ void __launch_bounds__(256, 1) node_kernel(
    const float* __restrict__ h,
    const float* __restrict__ Wn1, const float* __restrict__ bn1,
    const float* __restrict__ Wn2, const float* __restrict__ bn2,
    float* __restrict__ out_h, float* __restrict__ out_c)
{
    extern __shared__ float s[];
    const int tid = threadIdx.x;
    for (int i = tid; i < 8192; i += 256) s[i]         = Wn1[i];
    for (int i = tid; i < 64;   i += 256) s[8192 + i]  = bn1[i];
    for (int i = tid; i < 4096; i += 256) s[8256 + i]  = Wn2[i];
    for (int i = tid; i < 64;   i += 256) s[12352 + i] = bn2[i];
    __syncthreads();

    const int warp = tid >> 5, lane = tid & 31;
    float* stage = s + NODE_STAGE_BASE + warp * NODE_STAGE_STRIDE;

    const int nbase = blockIdx.x * 256 + warp * 32;
    const int n = nbase + lane;

    // stage h and agg transposed
    #pragma unroll 4
    for (int r = 0; r < 32; r++) {
        const int nr = nbase + r;
        if (nr < NN) {
            const float* hp = h + (size_t)nr * 64;
            const float* ap = g_agg + (size_t)nr * 64;
            stage[(lane)      * 33 + r] = hp[lane];
            stage[(lane + 32) * 33 + r] = hp[lane + 32];
            stage[(lane + 64) * 33 + r] = ap[lane];
            stage[(lane + 96) * 33 + r] = ap[lane + 32];
        } else {
            stage[(lane)      * 33 + r] = 0.f;
            stage[(lane + 32) * 33 + r] = 0.f;
            stage[(lane + 64) * 33 + r] = 0.f;
            stage[(lane + 96) * 33 + r] = 0.f;
        }
    }
    __syncwarp();

    // layer 1: hidden = relu([h,agg] @ Wn1 + bn1)
    float acc[64];
    #pragma unroll
    for (int t = 0; t < 64; t += 4) {
        float4 b = *(const float4*)(s + 8192 + t);
        acc[t] = b.x; acc[t + 1] = b.y; acc[t + 2] = b.z; acc[t + 3] = b.w;
    }
    for (int k = 0; k < 128; k++) {
        const float x = stage[k * 33 + lane];
        const float4* w = (const float4*)(s + k * 64);
        #pragma unroll
        for (int t = 0; t < 16; t++) {
            float4 wv = w[t];
            acc[4 * t + 0] += x * wv.x;
            acc[4 * t + 1] += x * wv.y;
            acc[4 * t + 2] += x * wv.z;
            acc[4 * t + 3] += x * wv.w;
        }
    }
    // store hidden into rows 64..127 (agg rows, no longer needed; h rows stay)
    #pragma unroll
    for (int t = 0; t < 64; t++) stage[(64 + t) * 33 + lane] = fmaxf(acc[t], 0.f);

    // layer 2: out = h + hidden @ Wn2 + bn2
    #pragma unroll
    for (int t = 0; t < 64; t += 4) {
        float4 b = *(const float4*)(s + 12352 + t);
        acc[t] = b.x; acc[t + 1] = b.y; acc[t + 2] = b.z; acc[t + 3] = b.w;
    }
    for (int k = 0; k < 64; k++) {
        const float x = stage[(64 + k) * 33 + lane];
        const float4* w = (const float4*)(s + 8256 + k * 64);
        #pragma unroll
        for (int t = 0; t < 16; t++) {
            float4 wv = w[t];
            acc[4 * t + 0] += x * wv.x;
            acc[4 * t + 1] += x * wv.y;
            acc[4 * t + 2] += x * wv.z;
            acc[4 * t + 3] += x * wv.w;
        }
    }

    if (n < NN) {
        float* op = out_h + (size_t)n * 64;
        #pragma unroll
        for (int t = 0; t < 64; t += 4) {
            float4 v;
            v.x = stage[(t + 0) * 33 + lane] + acc[t + 0];
            v.y = stage[(t + 1) * 33 + lane] + acc[t + 1];
            v.z = stage[(t + 2) * 33 + lane] + acc[t + 2];
            v.w = stage[(t + 3) * 33 + lane] + acc[t + 3];
            *(float4*)(op + t) = v;
        }
        const float inv = 1.f / fmaxf(g_cnt[n], 1.f);
        out_c[n * 3 + 0] = g_trans[n * 3 + 0] * inv;
        out_c[n * 3 + 1] = g_trans[n * 3 + 1] * inv;
        out_c[n * 3 + 2] = g_trans[n * 3 + 2] * inv;
    }
}

// ---------------- launch ----------------
extern "C" void kernel_launch(void* const* d_in, const int* in_sizes, int n_in,
                              void* d_out, int out_size)
{
    const float* h     = (const float*)d_in[0];
    const float* coord = (const float*)d_in[1];
    const int*   ei    = (const int*)  d_in[2];
    const float* We1 = (const float*)d_in[3];
    const float* be1 = (const float*)d_in[4];
    const float* We2 = (const float*)d_in[5];
    const float* be2 = (const float*)d_in[6];
    const float* Wn1 = (const float*)d_in[7];
    const float* bn1 = (const float*)d_in[8];
    const float* Wn2 = (const float*)d_in[9];
    const float* bn2 = (const float*)d_in[10];
    const float* Wc1 = (const float*)d_in[11];
    const float* bc1 = (const float*)d_in[12];
    const float* Wc2 = (const float*)d_in[13];

    float* out_h = (float*)d_out;                   // [N, 64]
    float* out_c = (float*)d_out + (size_t)NN * DD; // [N, 3]

    cudaFuncSetAttribute(edge_kernel, cudaFuncAttributeMaxDynamicSharedMemorySize, EDGE_SMEM_BYTES);
    cudaFuncSetAttribute(node_kernel, cudaFuncAttributeMaxDynamicSharedMemorySize, NODE_SMEM_BYTES);

    zero_kernel<<<1024, 256>>>();
    edge_kernel<<<148, 256, EDGE_SMEM_BYTES>>>(h, coord, ei,
                                               We1, be1, We2, be2, Wc1, bc1, Wc2);
    node_kernel<<<(NN + 255) / 256, 256, NODE_SMEM_BYTES>>>(h, Wn1, bn1, Wn2, bn2,
                                                            out_h, out_c);
}

// round 3
// speedup vs baseline: 1.2545x; 1.2545x over previous
#include <cuda_runtime.h>
#include <cstdint>

#define NN 50000
#define EE 1000000
#define DD 64

// ---------------- scratch (device globals; no allocation allowed) ----------------
__device__ float g_agg[NN * DD];     // segment_sum(edge_feat) per node
__device__ float g_trans[NN * 3];    // segment_sum(trans) per node
__device__ float g_cnt[NN];          // edge count per node

// ---------------- packed f32x2 helpers ----------------
__device__ __forceinline__ uint64_t pack2(float x, float y) {
    uint64_t r; asm("mov.b64 %0, {%1, %2};" : "=l"(r) : "f"(x), "f"(y)); return r;
}
__device__ __forceinline__ void unpack2(uint64_t v, float& x, float& y) {
    asm("mov.b64 {%0, %1}, %2;" : "=f"(x), "=f"(y) : "l"(v));
}
__device__ __forceinline__ void fma2(uint64_t& acc, uint64_t a, uint64_t b) {
    asm("fma.rn.f32x2 %0, %1, %2, %0;" : "+l"(acc) : "l"(a), "l"(b));
}
__device__ __forceinline__ void red4(float* p, float a, float b, float c, float d) {
    asm volatile("red.global.add.v4.f32 [%0], {%1, %2, %3, %4};"
                 :: "l"(p), "f"(a), "f"(b), "f"(c), "f"(d) : "memory");
}

// ---------------- zero scratch ----------------
__global__ void zero_kernel() {
    int i = blockIdx.x * blockDim.x + threadIdx.x;
    int stride = gridDim.x * blockDim.x;
    for (int j = i; j < NN * DD; j += stride) g_agg[j] = 0.f;
    for (int j = i; j < NN * 3;  j += stride) g_trans[j] = 0.f;
    for (int j = i; j < NN;      j += stride) g_cnt[j] = 0.f;
}

// ---------------- edge kernel ----------------
// lane = edge; 32 edges per warp-iteration. h gathered transposed into SMEM
// (stride-33, conflict-free). All MLP math as packed fma.rn.f32x2 with weights
// broadcast from SMEM via 128-bit loads. Layer-2/3 inputs stay in registers.
//
// SMEM float map:
//   [0,8256)      We1 (129x64)
//   [8256,8320)   be1
//   [8320,12416)  We2 (64x64)
//   [12416,12480) be2
//   [12480,16576) Wc1 (64x64)
//   [16576,16640) bc1
//   [16640,16704) Wc2 (64)
//   [16704, +8*4260)  per-warp stage buffers (129 rows x 33 cols, pad 4260)
//   [50784, +8*64)    per-warp index buffers
#define EDGE_STAGE_BASE 16704
#define EDGE_STAGE_STRIDE 4260
#define EDGE_IDX_BASE (EDGE_STAGE_BASE + 8 * EDGE_STAGE_STRIDE)   // 50784
#define EDGE_SMEM_FLOATS (EDGE_IDX_BASE + 8 * 64)                 // 51296
#define EDGE_SMEM_BYTES (EDGE_SMEM_FLOATS * 4)                    // 205184

__global__ void __launch_bounds__(256, 1) edge_kernel(
    const float* __restrict__ h, const float* __restrict__ coord,
    const int* __restrict__ ei,
    const float* __restrict__ We1, const float* __restrict__ be1,
    const float* __restrict__ We2, const float* __restrict__ be2,
    const float* __restrict__ Wc1, const float* __restrict__ bc1,
    const float* __restrict__ Wc2)
{
    extern __shared__ float s[];
    const int tid = threadIdx.x;

    for (int i = tid; i < 8256; i += 256) s[i]          = We1[i];
    for (int i = tid; i < 64;   i += 256) s[8256 + i]   = be1[i];
    for (int i = tid; i < 4096; i += 256) s[8320 + i]   = We2[i];
    for (int i = tid; i < 64;   i += 256) s[12416 + i]  = be2[i];
    for (int i = tid; i < 4096; i += 256) s[12480 + i]  = Wc1[i];
    for (int i = tid; i < 64;   i += 256) s[16576 + i]  = bc1[i];
    for (int i = tid; i < 64;   i += 256) s[16640 + i]  = Wc2[i];
    __syncthreads();

    const int warp = tid >> 5, lane = tid & 31;
    float* stage = s + EDGE_STAGE_BASE + warp * EDGE_STAGE_STRIDE;
    int*   iidx  = (int*)(s + EDGE_IDX_BASE + warp * 64);

    const int gw = blockIdx.x * 8 + warp;
    const int nwarps = gridDim.x * 8;
    const int niter = EE / 32;   // 31250 exactly

    for (int it = gw; it < niter; it += nwarps) {
        const int e = it * 32 + lane;
        const int row = ei[e];
        const int col = ei[EE + e];
        iidx[lane] = row;
        iidx[32 + lane] = col;

        const float dx = coord[row * 3 + 0] - coord[col * 3 + 0];
        const float dy = coord[row * 3 + 1] - coord[col * 3 + 1];
        const float dz = coord[row * 3 + 2] - coord[col * 3 + 2];
        const float radial = dx * dx + dy * dy + dz * dz;
        stage[128 * 33 + lane] = radial;
        __syncwarp();

        // gather h[row], h[col] -> transposed stage rows 0..127
        #pragma unroll 4
        for (int r = 0; r < 32; r++) {
            const int rr = iidx[r];
            const int cc = iidx[32 + r];
            const float* hr = h + (size_t)rr * 64;
            const float* hc = h + (size_t)cc * 64;
            stage[(lane)      * 33 + r] = hr[lane];
            stage[(lane + 32) * 33 + r] = hr[lane + 32];
            stage[(lane + 64) * 33 + r] = hc[lane];
            stage[(lane + 96) * 33 + r] = hc[lane + 32];
        }
        __syncwarp();

        uint64_t acc2[32];
        float m[64];

        // ---- layer 1: m = relu(e_in @ We1 + be1) ----
        {
            const uint64_t* b2 = (const uint64_t*)(s + 8256);
            #pragma unroll
            for (int t = 0; t < 32; t++) acc2[t] = b2[t];
        }
        for (int k = 0; k < 129; k++) {
            const float x = stage[k * 33 + lane];
            const uint64_t xx = pack2(x, x);
            const ulonglong2* w = (const ulonglong2*)(s + k * 64);
            #pragma unroll
            for (int t = 0; t < 16; t++) {
                ulonglong2 wv = w[t];
                fma2(acc2[2 * t + 0], xx, wv.x);
                fma2(acc2[2 * t + 1], xx, wv.y);
            }
        }
        #pragma unroll
        for (int t = 0; t < 32; t++) {
            float a, b; unpack2(acc2[t], a, b);
            m[2 * t + 0] = fmaxf(a, 0.f);
            m[2 * t + 1] = fmaxf(b, 0.f);
        }

        // ---- layer 2: ef = relu(m @ We2 + be2) ----
        {
            const uint64_t* b2 = (const uint64_t*)(s + 12416);
            #pragma unroll
            for (int t = 0; t < 32; t++) acc2[t] = b2[t];
        }
        for (int k = 0; k < 64; k++) {
            const uint64_t xx = pack2(m[k], m[k]);
            const ulonglong2* w = (const ulonglong2*)(s + 8320 + k * 64);
            #pragma unroll
            for (int t = 0; t < 16; t++) {
                ulonglong2 wv = w[t];
                fma2(acc2[2 * t + 0], xx, wv.x);
                fma2(acc2[2 * t + 1], xx, wv.y);
            }
        }
        #pragma unroll
        for (int t = 0; t < 32; t++) {
            float a, b; unpack2(acc2[t], a, b);
            m[2 * t + 0] = fmaxf(a, 0.f);   // m now holds edge_feat
            m[2 * t + 1] = fmaxf(b, 0.f);
        }

        // scatter edge_feat into g_agg (vector reductions, 16 insts)
        {
            float* dst = g_agg + (size_t)row * 64;
            #pragma unroll
            for (int t = 0; t < 16; t++)
                red4(dst + 4 * t, m[4 * t], m[4 * t + 1], m[4 * t + 2], m[4 * t + 3]);
        }

        // ---- layer 3: c = relu(ef @ Wc1 + bc1); gate = c . Wc2 ----
        {
            const uint64_t* b2 = (const uint64_t*)(s + 16576);
            #pragma unroll
            for (int t = 0; t < 32; t++) acc2[t] = b2[t];
        }
        for (int k = 0; k < 64; k++) {
            const uint64_t xx = pack2(m[k], m[k]);
            const ulonglong2* w = (const ulonglong2*)(s + 12480 + k * 64);
            #pragma unroll
            for (int t = 0; t < 16; t++) {
                ulonglong2 wv = w[t];
                fma2(acc2[2 * t + 0], xx, wv.x);
                fma2(acc2[2 * t + 1], xx, wv.y);
            }
        }
        float gate = 0.f;
        #pragma unroll
        for (int t = 0; t < 32; t++) {
            float a, b; unpack2(acc2[t], a, b);
            gate += fmaxf(a, 0.f) * s[16640 + 2 * t];
            gate += fmaxf(b, 0.f) * s[16640 + 2 * t + 1];
        }

        const float tx = fminf(fmaxf(dx * gate, -100.f), 100.f);
        const float ty = fminf(fmaxf(dy * gate, -100.f), 100.f);
        const float tz = fminf(fmaxf(dz * gate, -100.f), 100.f);
        atomicAdd(&g_trans[row * 3 + 0], tx);
        atomicAdd(&g_trans[row * 3 + 1], ty);
        atomicAdd(&g_trans[row * 3 + 2], tz);
        atomicAdd(&g_cnt[row], 1.f);
        __syncwarp();
    }
}

// ---------------- node kernel ----------------
#define NODE_STAGE_BASE 12416
#define NODE_STAGE_STRIDE 4224
#define NODE_SMEM_FLOATS (NODE_STAGE_BASE + 8 * NODE_STAGE_STRIDE)  // 46208
#define NODE_SMEM_BYTES (NODE_SMEM_FLOATS * 4)                      // 184832

__global__ void __launch_bounds__(256, 1) node_kernel(
    const float* __restrict__ h,
    const float* __restrict__ Wn1, const float* __restrict__ bn1,
    const float* __restrict__ Wn2, const float* __restrict__ bn2,
    float* __restrict__ out_h, float* __restrict__ out_c)
{
    extern __shared__ float s[];
    const int tid = threadIdx.x;
    for (int i = tid; i < 8192; i += 256) s[i]         = Wn1[i];
    for (int i = tid; i < 64;   i += 256) s[8192 + i]  = bn1[i];
    for (int i = tid; i < 4096; i += 256) s[8256 + i]  = Wn2[i];
    for (int i = tid; i < 64;   i += 256) s[12352 + i] = bn2[i];
    __syncthreads();

    const int warp = tid >> 5, lane = tid & 31;
    float* stage = s + NODE_STAGE_BASE + warp * NODE_STAGE_STRIDE;

    const int nbase = blockIdx.x * 256 + warp * 32;
    const int n = nbase + lane;

    // stage h and agg transposed (rows 0..63 = h, 64..127 = agg)
    #pragma unroll 4
    for (int r = 0; r < 32; r++) {
        const int nr = nbase + r;
        if (nr < NN) {
            const float* hp = h + (size_t)nr * 64;
            const float* ap = g_agg + (size_t)nr * 64;
            stage[(lane)      * 33 + r] = hp[lane];
            stage[(lane + 32) * 33 + r] = hp[lane + 32];
            stage[(lane + 64) * 33 + r] = ap[lane];
            stage[(lane + 96) * 33 + r] = ap[lane + 32];
        } else {
            stage[(lane)      * 33 + r] = 0.f;
            stage[(lane + 32) * 33 + r] = 0.f;
            stage[(lane + 64) * 33 + r] = 0.f;
            stage[(lane + 96) * 33 + r] = 0.f;
        }
    }
    __syncwarp();

    uint64_t acc2[32];
    float m[64];

    // layer 1: hidden = relu([h,agg] @ Wn1 + bn1)
    {
        const uint64_t* b2 = (const uint64_t*)(s + 8192);
        #pragma unroll
        for (int t = 0; t < 32; t++) acc2[t] = b2[t];
    }
    for (int k = 0; k < 128; k++) {
        const float x = stage[k * 33 + lane];
        const uint64_t xx = pack2(x, x);
        const ulonglong2* w = (const ulonglong2*)(s + k * 64);
        #pragma unroll
        for (int t = 0; t < 16; t++) {
            ulonglong2 wv = w[t];
            fma2(acc2[2 * t + 0], xx, wv.x);
            fma2(acc2[2 * t + 1], xx, wv.y);
        }
    }
    #pragma unroll
    for (int t = 0; t < 32; t++) {
        float a, b; unpack2(acc2[t], a, b);
        m[2 * t + 0] = fmaxf(a, 0.f);
        m[2 * t + 1] = fmaxf(b, 0.f);
    }

    // layer 2: out = h + hidden @ Wn2 + bn2
    {
        const uint64_t* b2 = (const uint64_t*)(s + 12352);
        #pragma unroll
        for (int t = 0; t < 32; t++) acc2[t] = b2[t];
    }
    for (int k = 0; k < 64; k++) {
        const uint64_t xx = pack2(m[k], m[k]);
        const ulonglong2* w = (const ulonglong2*)(s + 8256 + k * 64);
        #pragma unroll
        for (int t = 0; t < 16; t++) {
            ulonglong2 wv = w[t];
            fma2(acc2[2 * t + 0], xx, wv.x);
            fma2(acc2[2 * t + 1], xx, wv.y);
        }
    }

    if (n < NN) {
        float* op = out_h + (size_t)n * 64;
        #pragma unroll
        for (int t = 0; t < 16; t++) {
            float a, b, c, d;
            unpack2(acc2[2 * t + 0], a, b);
            unpack2(acc2[2 * t + 1], c, d);
            float4 v;
            v.x = stage[(4 * t + 0) * 33 + lane] + a;
            v.y = stage[(4 * t + 1) * 33 + lane] + b;
            v.z = stage[(4 * t + 2) * 33 + lane] + c;
            v.w = stage[(4 * t + 3) * 33 + lane] + d;
            *(float4*)(op + 4 * t) = v;
        }
        const float inv = 1.f / fmaxf(g_cnt[n], 1.f);
        out_c[n * 3 + 0] = g_trans[n * 3 + 0] * inv;
        out_c[n * 3 + 1] = g_trans[n * 3 + 1] * inv;
        out_c[n * 3 + 2] = g_trans[n * 3 + 2] * inv;
    }
}

// ---------------- launch ----------------
extern "C" void kernel_launch(void* const* d_in, const int* in_sizes, int n_in,
                              void* d_out, int out_size)
{
    const float* h     = (const float*)d_in[0];
    const float* coord = (const float*)d_in[1];
    const int*   ei    = (const int*)  d_in[2];
    const float* We1 = (const float*)d_in[3];
    const float* be1 = (const float*)d_in[4];
    const float* We2 = (const float*)d_in[5];
    const float* be2 = (const float*)d_in[6];
    const float* Wn1 = (const float*)d_in[7];
    const float* bn1 = (const float*)d_in[8];
    const float* Wn2 = (const float*)d_in[9];
    const float* bn2 = (const float*)d_in[10];
    const float* Wc1 = (const float*)d_in[11];
    const float* bc1 = (const float*)d_in[12];
    const float* Wc2 = (const float*)d_in[13];

    float* out_h = (float*)d_out;                   // [N, 64]
    float* out_c = (float*)d_out + (size_t)NN * DD; // [N, 3]

    cudaFuncSetAttribute(edge_kernel, cudaFuncAttributeMaxDynamicSharedMemorySize, EDGE_SMEM_BYTES);
    cudaFuncSetAttribute(node_kernel, cudaFuncAttributeMaxDynamicSharedMemorySize, NODE_SMEM_BYTES);

    zero_kernel<<<1024, 256>>>();
    edge_kernel<<<148, 256, EDGE_SMEM_BYTES>>>(h, coord, ei,
                                               We1, be1, We2, be2, Wc1, bc1, Wc2);
    node_kernel<<<(NN + 255) / 256, 256, NODE_SMEM_BYTES>>>(h, Wn1, bn1, Wn2, bn2,
                                                            out_h, out_c);
}

// round 4
// speedup vs baseline: 1.8331x; 1.4613x over previous
#include <cuda_runtime.h>
#include <cstdint>

#define NN 50000
#define EE 1000000
#define DD 64

// ---------------- scratch (device globals; no allocation allowed) ----------------
__device__ float g_agg[NN * DD];     // segment_sum(edge_feat) per node
__device__ float g_trans[NN * 3];    // segment_sum(trans) per node
__device__ float g_cnt[NN];          // edge count per node
__device__ float g_P[NN * DD];       // h @ We1[0:64] + be1
__device__ float g_Q[NN * DD];       // h @ We1[64:128]

// ---------------- packed f32x2 helpers ----------------
__device__ __forceinline__ uint64_t pack2(float x, float y) {
    uint64_t r; asm("mov.b64 %0, {%1, %2};" : "=l"(r) : "f"(x), "f"(y)); return r;
}
__device__ __forceinline__ void unpack2(uint64_t v, float& x, float& y) {
    asm("mov.b64 {%0, %1}, %2;" : "=f"(x), "=f"(y) : "l"(v));
}
__device__ __forceinline__ void fma2(uint64_t& acc, uint64_t a, uint64_t b) {
    asm("fma.rn.f32x2 %0, %1, %2, %0;" : "+l"(acc) : "l"(a), "l"(b));
}
__device__ __forceinline__ void red4(float* p, float a, float b, float c, float d) {
    asm volatile("red.global.add.v4.f32 [%0], {%1, %2, %3, %4};"
                 :: "l"(p), "f"(a), "f"(b), "f"(c), "f"(d) : "memory");
}

// ---------------- zero scratch ----------------
__global__ void zero_kernel() {
    int i = blockIdx.x * blockDim.x + threadIdx.x;
    int stride = gridDim.x * blockDim.x;
    for (int j = i; j < NN * DD; j += stride) g_agg[j] = 0.f;
    for (int j = i; j < NN * 3;  j += stride) g_trans[j] = 0.f;
    for (int j = i; j < NN;      j += stride) g_cnt[j] = 0.f;
}

// ---------------- pq kernel: P = h@We1[0:64] + be1, Q = h@We1[64:128] ----------------
// 256 threads, lane = node. stage 64x33 per warp.
// SMEM floats: [0,8192) We1 rows 0..127; [8192,8256) be1; [8256,+8*2112) stages.
#define PQ_STAGE_BASE 8256
#define PQ_STAGE_STRIDE 2112
#define PQ_SMEM_FLOATS (PQ_STAGE_BASE + 8 * PQ_STAGE_STRIDE)   // 25152
#define PQ_SMEM_BYTES (PQ_SMEM_FLOATS * 4)                      // 100608

__global__ void __launch_bounds__(256, 1) pq_kernel(
    const float* __restrict__ h,
    const float* __restrict__ We1, const float* __restrict__ be1)
{
    extern __shared__ float s[];
    const int tid = threadIdx.x;
    for (int i = tid; i < 8192; i += 256) s[i] = We1[i];
    for (int i = tid; i < 64;   i += 256) s[8192 + i] = be1[i];
    __syncthreads();

    const int warp = tid >> 5, lane = tid & 31;
    float* stage = s + PQ_STAGE_BASE + warp * PQ_STAGE_STRIDE;
    const int nbase = blockIdx.x * 256 + warp * 32;
    const int n = nbase + lane;

    // stage h transposed
    #pragma unroll 4
    for (int r = 0; r < 32; r++) {
        const int nr = nbase + r;
        if (nr < NN) {
            const float* hp = h + (size_t)nr * 64;
            stage[lane * 33 + r]        = hp[lane];
            stage[(lane + 32) * 33 + r] = hp[lane + 32];
        } else {
            stage[lane * 33 + r]        = 0.f;
            stage[(lane + 32) * 33 + r] = 0.f;
        }
    }
    __syncwarp();

    uint64_t acc2[32];

    // P = h @ We1[0:64] + be1
    {
        const uint64_t* b2 = (const uint64_t*)(s + 8192);
        #pragma unroll
        for (int t = 0; t < 32; t++) acc2[t] = b2[t];
    }
    for (int k = 0; k < 64; k++) {
        const float x = stage[k * 33 + lane];
        const uint64_t xx = pack2(x, x);
        const ulonglong2* w = (const ulonglong2*)(s + k * 64);
        #pragma unroll
        for (int t = 0; t < 16; t++) {
            ulonglong2 wv = w[t];
            fma2(acc2[2 * t + 0], xx, wv.x);
            fma2(acc2[2 * t + 1], xx, wv.y);
        }
    }
    if (n < NN) {
        float* op = g_P + (size_t)n * 64;
        #pragma unroll
        for (int t = 0; t < 16; t++) {
            float a, b, c, d;
            unpack2(acc2[2 * t + 0], a, b);
            unpack2(acc2[2 * t + 1], c, d);
            float4 v; v.x = a; v.y = b; v.z = c; v.w = d;
            *(float4*)(op + 4 * t) = v;
        }
    }

    // Q = h @ We1[64:128]
    #pragma unroll
    for (int t = 0; t < 32; t++) acc2[t] = 0ull;
    for (int k = 0; k < 64; k++) {
        const float x = stage[k * 33 + lane];
        const uint64_t xx = pack2(x, x);
        const ulonglong2* w = (const ulonglong2*)(s + (64 + k) * 64);
        #pragma unroll
        for (int t = 0; t < 16; t++) {
            ulonglong2 wv = w[t];
            fma2(acc2[2 * t + 0], xx, wv.x);
            fma2(acc2[2 * t + 1], xx, wv.y);
        }
    }
    if (n < NN) {
        float* op = g_Q + (size_t)n * 64;
        #pragma unroll
        for (int t = 0; t < 16; t++) {
            float a, b, c, d;
            unpack2(acc2[2 * t + 0], a, b);
            unpack2(acc2[2 * t + 1], c, d);
            float4 v; v.x = a; v.y = b; v.z = c; v.w = d;
            *(float4*)(op + 4 * t) = v;
        }
    }
}

// ---------------- edge kernel ----------------
// 128 threads/CTA, 3 CTAs/SM. lane = edge; 32 edges per warp-iteration.
// L1 is precomputed per node: m = relu(P[row] + Q[col] + radial*w128).
// The gather fuses P[row]+Q[col] into a single 64x33 stage.
//
// SMEM float map:
//   [0,64)        w128 (= We1 row 128)
//   [64,4160)     We2 (64x64)
//   [4160,4224)   be2
//   [4224,8320)   Wc1 (64x64)
//   [8320,8384)   bc1
//   [8384,8448)   Wc2 (64)
//   [8448, +4*2112)  per-warp stage (64 rows x 33)
//   [16896, +4*64)   per-warp index buffers
#define EDGE_STAGE_BASE 8448
#define EDGE_STAGE_STRIDE 2112
#define EDGE_IDX_BASE (EDGE_STAGE_BASE + 4 * EDGE_STAGE_STRIDE)   // 16896
#define EDGE_SMEM_FLOATS (EDGE_IDX_BASE + 4 * 64)                 // 17152
#define EDGE_SMEM_BYTES (EDGE_SMEM_FLOATS * 4)                    // 68608

__global__ void __launch_bounds__(128, 3) edge_kernel(
    const float* __restrict__ coord,
    const int* __restrict__ ei,
    const float* __restrict__ We1,   // only row 128 used (w128)
    const float* __restrict__ We2, const float* __restrict__ be2,
    const float* __restrict__ Wc1, const float* __restrict__ bc1,
    const float* __restrict__ Wc2)
{
    extern __shared__ float s[];
    const int tid = threadIdx.x;

    for (int i = tid; i < 64;   i += 128) s[i]        = We1[128 * 64 + i];
    for (int i = tid; i < 4096; i += 128) s[64 + i]   = We2[i];
    for (int i = tid; i < 64;   i += 128) s[4160 + i] = be2[i];
    for (int i = tid; i < 4096; i += 128) s[4224 + i] = Wc1[i];
    for (int i = tid; i < 64;   i += 128) s[8320 + i] = bc1[i];
    for (int i = tid; i < 64;   i += 128) s[8384 + i] = Wc2[i];
    __syncthreads();

    const int warp = tid >> 5, lane = tid & 31;
    float* stage = s + EDGE_STAGE_BASE + warp * EDGE_STAGE_STRIDE;
    int*   iidx  = (int*)(s + EDGE_IDX_BASE + warp * 64);

    const int gw = blockIdx.x * 4 + warp;
    const int nwarps = gridDim.x * 4;
    const int niter = EE / 32;   // 31250 exactly

    for (int it = gw; it < niter; it += nwarps) {
        const int e = it * 32 + lane;
        const int row = ei[e];
        const int col = ei[EE + e];
        iidx[lane] = row;
        iidx[32 + lane] = col;

        const float dx = coord[row * 3 + 0] - coord[col * 3 + 0];
        const float dy = coord[row * 3 + 1] - coord[col * 3 + 1];
        const float dz = coord[row * 3 + 2] - coord[col * 3 + 2];
        const float radial = dx * dx + dy * dy + dz * dz;
        __syncwarp();

        // gather P[row]+Q[col] -> transposed stage rows 0..63
        #pragma unroll 4
        for (int r = 0; r < 32; r++) {
            const int rr = iidx[r];
            const int cc = iidx[32 + r];
            const float* Pr = g_P + (size_t)rr * 64;
            const float* Qc = g_Q + (size_t)cc * 64;
            stage[lane * 33 + r]        = Pr[lane]      + Qc[lane];
            stage[(lane + 32) * 33 + r] = Pr[lane + 32] + Qc[lane + 32];
        }
        __syncwarp();

        // ---- layer 1 (factored): m = relu(stage + radial*w128) ----
        float m[64];
        #pragma unroll
        for (int t = 0; t < 64; t += 4) {
            float4 w = *(const float4*)(s + t);
            m[t + 0] = fmaxf(fmaf(radial, w.x, stage[(t + 0) * 33 + lane]), 0.f);
            m[t + 1] = fmaxf(fmaf(radial, w.y, stage[(t + 1) * 33 + lane]), 0.f);
            m[t + 2] = fmaxf(fmaf(radial, w.z, stage[(t + 2) * 33 + lane]), 0.f);
            m[t + 3] = fmaxf(fmaf(radial, w.w, stage[(t + 3) * 33 + lane]), 0.f);
        }

        uint64_t acc2[32];

        // ---- layer 2: ef = relu(m @ We2 + be2) ----
        {
            const uint64_t* b2 = (const uint64_t*)(s + 4160);
            #pragma unroll
            for (int t = 0; t < 32; t++) acc2[t] = b2[t];
        }
        #pragma unroll
        for (int k = 0; k < 64; k++) {
            const uint64_t xx = pack2(m[k], m[k]);
            const ulonglong2* w = (const ulonglong2*)(s + 64 + k * 64);
            #pragma unroll
            for (int t = 0; t < 16; t++) {
                ulonglong2 wv = w[t];
                fma2(acc2[2 * t + 0], xx, wv.x);
                fma2(acc2[2 * t + 1], xx, wv.y);
            }
        }
        #pragma unroll
        for (int t = 0; t < 32; t++) {
            float a, b; unpack2(acc2[t], a, b);
            m[2 * t + 0] = fmaxf(a, 0.f);   // m now holds edge_feat
            m[2 * t + 1] = fmaxf(b, 0.f);
        }

        // scatter edge_feat into g_agg (vector reductions)
        {
            float* dst = g_agg + (size_t)row * 64;
            #pragma unroll
            for (int t = 0; t < 16; t++)
                red4(dst + 4 * t, m[4 * t], m[4 * t + 1], m[4 * t + 2], m[4 * t + 3]);
        }

        // ---- layer 3: c = relu(ef @ Wc1 + bc1); gate = c . Wc2 ----
        {
            const uint64_t* b2 = (const uint64_t*)(s + 8320);
            #pragma unroll
            for (int t = 0; t < 32; t++) acc2[t] = b2[t];
        }
        #pragma unroll
        for (int k = 0; k < 64; k++) {
            const uint64_t xx = pack2(m[k], m[k]);
            const ulonglong2* w = (const ulonglong2*)(s + 4224 + k * 64);
            #pragma unroll
            for (int t = 0; t < 16; t++) {
                ulonglong2 wv = w[t];
                fma2(acc2[2 * t + 0], xx, wv.x);
                fma2(acc2[2 * t + 1], xx, wv.y);
            }
        }
        float gate = 0.f;
        #pragma unroll
        for (int t = 0; t < 32; t++) {
            float a, b; unpack2(acc2[t], a, b);
            gate += fmaxf(a, 0.f) * s[8384 + 2 * t];
            gate += fmaxf(b, 0.f) * s[8384 + 2 * t + 1];
        }

        const float tx = fminf(fmaxf(dx * gate, -100.f), 100.f);
        const float ty = fminf(fmaxf(dy * gate, -100.f), 100.f);
        const float tz = fminf(fmaxf(dz * gate, -100.f), 100.f);
        atomicAdd(&g_trans[row * 3 + 0], tx);
        atomicAdd(&g_trans[row * 3 + 1], ty);
        atomicAdd(&g_trans[row * 3 + 2], tz);
        atomicAdd(&g_cnt[row], 1.f);
        __syncwarp();
    }
}

// ---------------- node kernel ----------------
#define NODE_STAGE_BASE 12416
#define NODE_STAGE_STRIDE 4224
#define NODE_SMEM_FLOATS (NODE_STAGE_BASE + 8 * NODE_STAGE_STRIDE)  // 46208
#define NODE_SMEM_BYTES (NODE_SMEM_FLOATS * 4)                      // 184832

__global__ void __launch_bounds__(256, 1) node_kernel(
    const float* __restrict__ h,
    const float* __restrict__ Wn1, const float* __restrict__ bn1,
    const float* __restrict__ Wn2, const float* __restrict__ bn2,
    float* __restrict__ out_h, float* __restrict__ out_c)
{
    extern __shared__ float s[];
    const int tid = threadIdx.x;
    for (int i = tid; i < 8192; i += 256) s[i]         = Wn1[i];
    for (int i = tid; i < 64;   i += 256) s[8192 + i]  = bn1[i];
    for (int i = tid; i < 4096; i += 256) s[8256 + i]  = Wn2[i];
    for (int i = tid; i < 64;   i += 256) s[12352 + i] = bn2[i];
    __syncthreads();

    const int warp = tid >> 5, lane = tid & 31;
    float* stage = s + NODE_STAGE_BASE + warp * NODE_STAGE_STRIDE;

    const int nbase = blockIdx.x * 256 + warp * 32;
    const int n = nbase + lane;

    #pragma unroll 4
    for (int r = 0; r < 32; r++) {
        const int nr = nbase + r;
        if (nr < NN) {
            const float* hp = h + (size_t)nr * 64;
            const float* ap = g_agg + (size_t)nr * 64;
            stage[(lane)      * 33 + r] = hp[lane];
            stage[(lane + 32) * 33 + r] = hp[lane + 32];
            stage[(lane + 64) * 33 + r] = ap[lane];
            stage[(lane + 96) * 33 + r] = ap[lane + 32];
        } else {
            stage[(lane)      * 33 + r] = 0.f;
            stage[(lane + 32) * 33 + r] = 0.f;
            stage[(lane + 64) * 33 + r] = 0.f;
            stage[(lane + 96) * 33 + r] = 0.f;
        }
    }
    __syncwarp();

    uint64_t acc2[32];
    float m[64];

    {
        const uint64_t* b2 = (const uint64_t*)(s + 8192);
        #pragma unroll
        for (int t = 0; t < 32; t++) acc2[t] = b2[t];
    }
    for (int k = 0; k < 128; k++) {
        const float x = stage[k * 33 + lane];
        const uint64_t xx = pack2(x, x);
        const ulonglong2* w = (const ulonglong2*)(s + k * 64);
        #pragma unroll
        for (int t = 0; t < 16; t++) {
            ulonglong2 wv = w[t];
            fma2(acc2[2 * t + 0], xx, wv.x);
            fma2(acc2[2 * t + 1], xx, wv.y);
        }
    }
    #pragma unroll
    for (int t = 0; t < 32; t++) {
        float a, b; unpack2(acc2[t], a, b);
        m[2 * t + 0] = fmaxf(a, 0.f);
        m[2 * t + 1] = fmaxf(b, 0.f);
    }

    {
        const uint64_t* b2 = (const uint64_t*)(s + 12352);
        #pragma unroll
        for (int t = 0; t < 32; t++) acc2[t] = b2[t];
    }
    #pragma unroll
    for (int k = 0; k < 64; k++) {
        const uint64_t xx = pack2(m[k], m[k]);
        const ulonglong2* w = (const ulonglong2*)(s + 8256 + k * 64);
        #pragma unroll
        for (int t = 0; t < 16; t++) {
            ulonglong2 wv = w[t];
            fma2(acc2[2 * t + 0], xx, wv.x);
            fma2(acc2[2 * t + 1], xx, wv.y);
        }
    }

    if (n < NN) {
        float* op = out_h + (size_t)n * 64;
        #pragma unroll
        for (int t = 0; t < 16; t++) {
            float a, b, c, d;
            unpack2(acc2[2 * t + 0], a, b);
            unpack2(acc2[2 * t + 1], c, d);
            float4 v;
            v.x = stage[(4 * t + 0) * 33 + lane] + a;
            v.y = stage[(4 * t + 1) * 33 + lane] + b;
            v.z = stage[(4 * t + 2) * 33 + lane] + c;
            v.w = stage[(4 * t + 3) * 33 + lane] + d;
            *(float4*)(op + 4 * t) = v;
        }
        const float inv = 1.f / fmaxf(g_cnt[n], 1.f);
        out_c[n * 3 + 0] = g_trans[n * 3 + 0] * inv;
        out_c[n * 3 + 1] = g_trans[n * 3 + 1] * inv;
        out_c[n * 3 + 2] = g_trans[n * 3 + 2] * inv;
    }
}

// ---------------- launch ----------------
extern "C" void kernel_launch(void* const* d_in, const int* in_sizes, int n_in,
                              void* d_out, int out_size)
{
    const float* h     = (const float*)d_in[0];
    const float* coord = (const float*)d_in[1];
    const int*   ei    = (const int*)  d_in[2];
    const float* We1 = (const float*)d_in[3];
    const float* be1 = (const float*)d_in[4];
    const float* We2 = (const float*)d_in[5];
    const float* be2 = (const float*)d_in[6];
    const float* Wn1 = (const float*)d_in[7];
    const float* bn1 = (const float*)d_in[8];
    const float* Wn2 = (const float*)d_in[9];
    const float* bn2 = (const float*)d_in[10];
    const float* Wc1 = (const float*)d_in[11];
    const float* bc1 = (const float*)d_in[12];
    const float* Wc2 = (const float*)d_in[13];

    float* out_h = (float*)d_out;                   // [N, 64]
    float* out_c = (float*)d_out + (size_t)NN * DD; // [N, 3]

    cudaFuncSetAttribute(pq_kernel,   cudaFuncAttributeMaxDynamicSharedMemorySize, PQ_SMEM_BYTES);
    cudaFuncSetAttribute(edge_kernel, cudaFuncAttributeMaxDynamicSharedMemorySize, EDGE_SMEM_BYTES);
    cudaFuncSetAttribute(node_kernel, cudaFuncAttributeMaxDynamicSharedMemorySize, NODE_SMEM_BYTES);

    zero_kernel<<<1024, 256>>>();
    pq_kernel<<<(NN + 255) / 256, 256, PQ_SMEM_BYTES>>>(h, We1, be1);
    edge_kernel<<<444, 128, EDGE_SMEM_BYTES>>>(coord, ei, We1,
                                               We2, be2, Wc1, bc1, Wc2);
    node_kernel<<<(NN + 255) / 256, 256, NODE_SMEM_BYTES>>>(h, Wn1, bn1, Wn2, bn2,
                                                            out_h, out_c);
}

// round 6
// speedup vs baseline: 2.4658x; 1.3452x over previous
#include <cuda_runtime.h>
#include <cuda_bf16.h>
#include <mma.h>
#include <cstdint>

using namespace nvcuda;

#define NN 50000
#define EE 1000000
#define DD 64
#define TILE 64
#define NT (EE / TILE)   // 15625 exactly

// ---------------- scratch (device globals; no allocation allowed) ----------------
__device__ float g_agg[NN * DD];
__device__ float g_trans[NN * 3];
__device__ float g_cnt[NN];
__device__ float g_P[NN * DD];       // h @ We1[0:64] + be1
__device__ float g_Q[NN * DD];       // h @ We1[64:128]

__device__ __forceinline__ void red4(float* p, float a, float b, float c, float d) {
    asm volatile("red.global.add.v4.f32 [%0], {%1, %2, %3, %4};"
                 :: "l"(p), "f"(a), "f"(b), "f"(c), "f"(d) : "memory");
}
__device__ __forceinline__ uint64_t pack2(float x, float y) {
    uint64_t r; asm("mov.b64 %0, {%1, %2};" : "=l"(r) : "f"(x), "f"(y)); return r;
}
__device__ __forceinline__ void unpack2(uint64_t v, float& x, float& y) {
    asm("mov.b64 {%0, %1}, %2;" : "=f"(x), "=f"(y) : "l"(v));
}
__device__ __forceinline__ void fma2(uint64_t& acc, uint64_t a, uint64_t b) {
    asm("fma.rn.f32x2 %0, %1, %2, %0;" : "+l"(acc) : "l"(a), "l"(b));
}
__device__ __forceinline__ uint32_t bf2u(__nv_bfloat162 v) {
    uint32_t u; memcpy(&u, &v, 4); return u;
}

// ---------------- zero scratch ----------------
__global__ void zero_kernel() {
    int i = blockIdx.x * blockDim.x + threadIdx.x;
    int stride = gridDim.x * blockDim.x;
    for (int j = i; j < NN * DD; j += stride) g_agg[j] = 0.f;
    for (int j = i; j < NN * 3;  j += stride) g_trans[j] = 0.f;
    for (int j = i; j < NN;      j += stride) g_cnt[j] = 0.f;
}

// ---------------- pq kernel (unchanged from R4) ----------------
#define PQ_STAGE_BASE 8256
#define PQ_STAGE_STRIDE 2112
#define PQ_SMEM_FLOATS (PQ_STAGE_BASE + 8 * PQ_STAGE_STRIDE)
#define PQ_SMEM_BYTES (PQ_SMEM_FLOATS * 4)

__global__ void __launch_bounds__(256, 1) pq_kernel(
    const float* __restrict__ h,
    const float* __restrict__ We1, const float* __restrict__ be1)
{
    extern __shared__ float s[];
    const int tid = threadIdx.x;
    for (int i = tid; i < 8192; i += 256) s[i] = We1[i];
    for (int i = tid; i < 64;   i += 256) s[8192 + i] = be1[i];
    __syncthreads();

    const int warp = tid >> 5, lane = tid & 31;
    float* stage = s + PQ_STAGE_BASE + warp * PQ_STAGE_STRIDE;
    const int nbase = blockIdx.x * 256 + warp * 32;
    const int n = nbase + lane;

    #pragma unroll 4
    for (int r = 0; r < 32; r++) {
        const int nr = nbase + r;
        if (nr < NN) {
            const float* hp = h + (size_t)nr * 64;
            stage[lane * 33 + r]        = hp[lane];
            stage[(lane + 32) * 33 + r] = hp[lane + 32];
        } else {
            stage[lane * 33 + r]        = 0.f;
            stage[(lane + 32) * 33 + r] = 0.f;
        }
    }
    __syncwarp();

    uint64_t acc2[32];
    {
        const uint64_t* b2 = (const uint64_t*)(s + 8192);
        #pragma unroll
        for (int t = 0; t < 32; t++) acc2[t] = b2[t];
    }
    for (int k = 0; k < 64; k++) {
        const float x = stage[k * 33 + lane];
        const uint64_t xx = pack2(x, x);
        const ulonglong2* w = (const ulonglong2*)(s + k * 64);
        #pragma unroll
        for (int t = 0; t < 16; t++) {
            ulonglong2 wv = w[t];
            fma2(acc2[2 * t + 0], xx, wv.x);
            fma2(acc2[2 * t + 1], xx, wv.y);
        }
    }
    if (n < NN) {
        float* op = g_P + (size_t)n * 64;
        #pragma unroll
        for (int t = 0; t < 16; t++) {
            float a, b, c, d;
            unpack2(acc2[2 * t + 0], a, b);
            unpack2(acc2[2 * t + 1], c, d);
            float4 v; v.x = a; v.y = b; v.z = c; v.w = d;
            *(float4*)(op + 4 * t) = v;
        }
    }

    #pragma unroll
    for (int t = 0; t < 32; t++) acc2[t] = 0ull;
    for (int k = 0; k < 64; k++) {
        const float x = stage[k * 33 + lane];
        const uint64_t xx = pack2(x, x);
        const ulonglong2* w = (const ulonglong2*)(s + (64 + k) * 64);
        #pragma unroll
        for (int t = 0; t < 16; t++) {
            ulonglong2 wv = w[t];
            fma2(acc2[2 * t + 0], xx, wv.x);
            fma2(acc2[2 * t + 1], xx, wv.y);
        }
    }
    if (n < NN) {
        float* op = g_Q + (size_t)n * 64;
        #pragma unroll
        for (int t = 0; t < 16; t++) {
            float a, b, c, d;
            unpack2(acc2[2 * t + 0], a, b);
            unpack2(acc2[2 * t + 1], c, d);
            float4 v; v.x = a; v.y = b; v.z = c; v.w = d;
            *(float4*)(op + 4 * t) = v;
        }
    }
}

// ---------------- edge kernel: wmma bf16 hi/lo ----------------
// 128 threads/CTA, 2 CTAs/SM, persistent over 64-edge tiles.
// SMEM byte map (16B aligned):
//   floats s[]: w128 @0..63, be2 @64, bc1 @128, wc2 @192,
//               irow @256(int), icol @320, frad @384, fdx @448, fdy @512, fdz @576
//   bf16 tiles (stride 72): WE2H @4096, WE2L @13312, WC1H @22528, WC1L @31744,
//                           AH @40960, AL @50176   (64x72x2 = 9216 B each)
//   f32 D (stride 68): @59392, 64x68x4 = 17408 B  -> total 76800
#define EB_WE2H 4096
#define EB_WE2L 13312
#define EB_WC1H 22528
#define EB_WC1L 31744
#define EB_AH   40960
#define EB_AL   50176
#define EB_D    59392
#define EDGE_SMEM_BYTES 76800

__device__ __forceinline__ void gemm_hilo(char* sc, int whOff, int wlOff, int wid) {
    wmma::fragment<wmma::accumulator, 16, 16, 16, float> acc[4];
    #pragma unroll
    for (int ct = 0; ct < 4; ct++) wmma::fill_fragment(acc[ct], 0.f);

    const __nv_bfloat16* Ah = (const __nv_bfloat16*)(sc + EB_AH) + wid * 16 * 72;
    const __nv_bfloat16* Al = (const __nv_bfloat16*)(sc + EB_AL) + wid * 16 * 72;
    const __nv_bfloat16* Wh = (const __nv_bfloat16*)(sc + whOff);
    const __nv_bfloat16* Wl = (const __nv_bfloat16*)(sc + wlOff);

    #pragma unroll
    for (int k0 = 0; k0 < 4; k0++) {
        wmma::fragment<wmma::matrix_a, 16, 16, 16, __nv_bfloat16, wmma::row_major> a_h, a_l;
        wmma::load_matrix_sync(a_h, Ah + k0 * 16, 72);
        wmma::load_matrix_sync(a_l, Al + k0 * 16, 72);
        #pragma unroll
        for (int ct = 0; ct < 4; ct++) {
            wmma::fragment<wmma::matrix_b, 16, 16, 16, __nv_bfloat16, wmma::row_major> b_h, b_l;
            wmma::load_matrix_sync(b_h, Wh + k0 * 16 * 72 + ct * 16, 72);
            wmma::load_matrix_sync(b_l, Wl + k0 * 16 * 72 + ct * 16, 72);
            wmma::mma_sync(acc[ct], a_h, b_h, acc[ct]);
            wmma::mma_sync(acc[ct], a_l, b_h, acc[ct]);
            wmma::mma_sync(acc[ct], a_h, b_l, acc[ct]);
        }
    }
    float* Dp = (float*)(sc + EB_D) + wid * 16 * 68;
    #pragma unroll
    for (int ct = 0; ct < 4; ct++)
        wmma::store_matrix_sync(Dp + ct * 16, acc[ct], 68, wmma::mem_row_major);
}

__global__ void __launch_bounds__(128, 2) edge_kernel(
    const float* __restrict__ coord,
    const int* __restrict__ ei,
    const float* __restrict__ We1,   // row 128 only
    const float* __restrict__ We2,
    const float* __restrict__ Wc1, const float* __restrict__ be2,
    const float* __restrict__ bc1, const float* __restrict__ Wc2)
{
    extern __shared__ __align__(16) char sc[];
    float* s = (float*)sc;

    const int tid = threadIdx.x;
    const int wid = tid >> 5;

    // scalars
    for (int i = tid; i < 64; i += 128) {
        s[i]        = We1[128 * 64 + i];
        s[64 + i]   = be2[i];
        s[128 + i]  = bc1[i];
        s[192 + i]  = Wc2[i];
    }
    // weight tiles: [k][n] row-major, stride 72, hi/lo bf16
    for (int i = tid; i < 4096; i += 128) {
        const int k = i >> 6, n = i & 63;
        {
            float v = We2[i];
            __nv_bfloat16 hb = __float2bfloat16(v);
            __nv_bfloat16 lb = __float2bfloat16(v - __bfloat162float(hb));
            ((__nv_bfloat16*)(sc + EB_WE2H))[k * 72 + n] = hb;
            ((__nv_bfloat16*)(sc + EB_WE2L))[k * 72 + n] = lb;
        }
        {
            float v = Wc1[i];
            __nv_bfloat16 hb = __float2bfloat16(v);
            __nv_bfloat16 lb = __float2bfloat16(v - __bfloat162float(hb));
            ((__nv_bfloat16*)(sc + EB_WC1H))[k * 72 + n] = hb;
            ((__nv_bfloat16*)(sc + EB_WC1L))[k * 72 + n] = lb;
        }
    }

    int*   irow = (int*)(s + 256);
    int*   icol = (int*)(s + 320);
    float* frad = s + 384;
    float* fdx  = s + 448;
    float* fdy  = s + 512;
    float* fdz  = s + 576;

    const int r = tid >> 1;          // edge row within tile (0..63)
    const int hh = tid & 1;          // column half (0/1)
    const int c0 = hh * 32;

    for (int t = blockIdx.x; t < NT; t += gridDim.x) {
        __syncthreads();   // protect smem from previous iteration
        if (tid < TILE) {
            const int e = t * TILE + tid;
            const int row = ei[e];
            const int col = ei[EE + e];
            irow[tid] = row;
            icol[tid] = col;
            const float dx = coord[row * 3 + 0] - coord[col * 3 + 0];
            const float dy = coord[row * 3 + 1] - coord[col * 3 + 1];
            const float dz = coord[row * 3 + 2] - coord[col * 3 + 2];
            fdx[tid] = dx; fdy[tid] = dy; fdz[tid] = dz;
            frad[tid] = dx * dx + dy * dy + dz * dz;
        }
        __syncthreads();

        // ---- build A1 = relu(P[row]+Q[col]+rad*w128) hi/lo; thread = (row, half)
        {
            const int rr = irow[r], cc = icol[r];
            const float rad = frad[r];
            const float4* Pp = (const float4*)(g_P + (size_t)rr * 64 + c0);
            const float4* Qp = (const float4*)(g_Q + (size_t)cc * 64 + c0);
            const float4* wp = (const float4*)(s + c0);
            uint2* ah = (uint2*)(sc + EB_AH + r * 144 + hh * 64);
            uint2* al = (uint2*)(sc + EB_AL + r * 144 + hh * 64);
            #pragma unroll
            for (int j = 0; j < 8; j++) {
                float4 p = Pp[j], q = Qp[j], w = wp[j];
                const float v0 = fmaxf(fmaf(rad, w.x, p.x + q.x), 0.f);
                const float v1 = fmaxf(fmaf(rad, w.y, p.y + q.y), 0.f);
                const float v2 = fmaxf(fmaf(rad, w.z, p.z + q.z), 0.f);
                const float v3 = fmaxf(fmaf(rad, w.w, p.w + q.w), 0.f);
                __nv_bfloat162 h01 = __floats2bfloat162_rn(v0, v1);
                __nv_bfloat162 h23 = __floats2bfloat162_rn(v2, v3);
                __nv_bfloat162 l01 = __floats2bfloat162_rn(v0 - __bfloat162float(h01.x),
                                                           v1 - __bfloat162float(h01.y));
                __nv_bfloat162 l23 = __floats2bfloat162_rn(v2 - __bfloat162float(h23.x),
                                                           v3 - __bfloat162float(h23.y));
                ah[j] = make_uint2(bf2u(h01), bf2u(h23));
                al[j] = make_uint2(bf2u(l01), bf2u(l23));
            }
        }
        __syncthreads();

        // ---- GEMM1: D = A1 @ We2 ----
        gemm_hilo(sc, EB_WE2H, EB_WE2L, wid);
        __syncthreads();

        // ---- epilogue 1: ef = relu(D + be2); scatter; build A2 hi/lo ----
        {
            const float4* Dr = (const float4*)((float*)(sc + EB_D) + r * 68 + c0);
            const float4* bb = (const float4*)(s + 64 + c0);
            float ef[32];
            #pragma unroll
            for (int j = 0; j < 8; j++) {
                float4 d = Dr[j], b = bb[j];
                ef[4 * j + 0] = fmaxf(d.x + b.x, 0.f);
                ef[4 * j + 1] = fmaxf(d.y + b.y, 0.f);
                ef[4 * j + 2] = fmaxf(d.z + b.z, 0.f);
                ef[4 * j + 3] = fmaxf(d.w + b.w, 0.f);
            }
            float* dst = g_agg + (size_t)irow[r] * 64 + c0;
            #pragma unroll
            for (int j = 0; j < 8; j++)
                red4(dst + 4 * j, ef[4 * j], ef[4 * j + 1], ef[4 * j + 2], ef[4 * j + 3]);

            uint2* ah = (uint2*)(sc + EB_AH + r * 144 + hh * 64);
            uint2* al = (uint2*)(sc + EB_AL + r * 144 + hh * 64);
            #pragma unroll
            for (int j = 0; j < 8; j++) {
                const float v0 = ef[4 * j + 0], v1 = ef[4 * j + 1];
                const float v2 = ef[4 * j + 2], v3 = ef[4 * j + 3];
                __nv_bfloat162 h01 = __floats2bfloat162_rn(v0, v1);
                __nv_bfloat162 h23 = __floats2bfloat162_rn(v2, v3);
                __nv_bfloat162 l01 = __floats2bfloat162_rn(v0 - __bfloat162float(h01.x),
                                                           v1 - __bfloat162float(h01.y));
                __nv_bfloat162 l23 = __floats2bfloat162_rn(v2 - __bfloat162float(h23.x),
                                                           v3 - __bfloat162float(h23.y));
                ah[j] = make_uint2(bf2u(h01), bf2u(h23));
                al[j] = make_uint2(bf2u(l01), bf2u(l23));
            }
        }
        __syncthreads();

        // ---- GEMM2: D = EF @ Wc1 ----
        gemm_hilo(sc, EB_WC1H, EB_WC1L, wid);
        __syncthreads();

        // ---- epilogue 2: gate = relu(D + bc1) . wc2; clamp; coord atomics ----
        {
            const float4* Dr = (const float4*)((float*)(sc + EB_D) + r * 68 + c0);
            const float4* bb = (const float4*)(s + 128 + c0);
            const float4* wc = (const float4*)(s + 192 + c0);
            float g = 0.f;
            #pragma unroll
            for (int j = 0; j < 8; j++) {
                float4 d = Dr[j], b = bb[j], w = wc[j];
                g += fmaxf(d.x + b.x, 0.f) * w.x;
                g += fmaxf(d.y + b.y, 0.f) * w.y;
                g += fmaxf(d.z + b.z, 0.f) * w.z;
                g += fmaxf(d.w + b.w, 0.f) * w.w;
            }
            g += __shfl_xor_sync(0xFFFFFFFFu, g, 1);
            if (hh == 0) {
                const int row = irow[r];
                const float tx = fminf(fmaxf(fdx[r] * g, -100.f), 100.f);
                const float ty = fminf(fmaxf(fdy[r] * g, -100.f), 100.f);
                const float tz = fminf(fmaxf(fdz[r] * g, -100.f), 100.f);
                atomicAdd(&g_trans[row * 3 + 0], tx);
                atomicAdd(&g_trans[row * 3 + 1], ty);
                atomicAdd(&g_trans[row * 3 + 2], tz);
                atomicAdd(&g_cnt[row], 1.f);
            }
        }
    }
}

// ---------------- node kernel (unchanged from R4) ----------------
#define NODE_STAGE_BASE 12416
#define NODE_STAGE_STRIDE 4224
#define NODE_SMEM_FLOATS (NODE_STAGE_BASE + 8 * NODE_STAGE_STRIDE)
#define NODE_SMEM_BYTES (NODE_SMEM_FLOATS * 4)

__global__ void __launch_bounds__(256, 1) node_kernel(
    const float* __restrict__ h,
    const float* __restrict__ Wn1, const float* __restrict__ bn1,
    const float* __restrict__ Wn2, const float* __restrict__ bn2,
    float* __restrict__ out_h, float* __restrict__ out_c)
{
    extern __shared__ float s[];
    const int tid = threadIdx.x;
    for (int i = tid; i < 8192; i += 256) s[i]         = Wn1[i];
    for (int i = tid; i < 64;   i += 256) s[8192 + i]  = bn1[i];
    for (int i = tid; i < 4096; i += 256) s[8256 + i]  = Wn2[i];
    for (int i = tid; i < 64;   i += 256) s[12352 + i] = bn2[i];
    __syncthreads();

    const int warp = tid >> 5, lane = tid & 31;
    float* stage = s + NODE_STAGE_BASE + warp * NODE_STAGE_STRIDE;

    const int nbase = blockIdx.x * 256 + warp * 32;
    const int n = nbase + lane;

    #pragma unroll 4
    for (int r = 0; r < 32; r++) {
        const int nr = nbase + r;
        if (nr < NN) {
            const float* hp = h + (size_t)nr * 64;
            const float* ap = g_agg + (size_t)nr * 64;
            stage[(lane)      * 33 + r] = hp[lane];
            stage[(lane + 32) * 33 + r] = hp[lane + 32];
            stage[(lane + 64) * 33 + r] = ap[lane];
            stage[(lane + 96) * 33 + r] = ap[lane + 32];
        } else {
            stage[(lane)      * 33 + r] = 0.f;
            stage[(lane + 32) * 33 + r] = 0.f;
            stage[(lane + 64) * 33 + r] = 0.f;
            stage[(lane + 96) * 33 + r] = 0.f;
        }
    }
    __syncwarp();

    uint64_t acc2[32];
    float m[64];

    {
        const uint64_t* b2 = (const uint64_t*)(s + 8192);
        #pragma unroll
        for (int t = 0; t < 32; t++) acc2[t] = b2[t];
    }
    for (int k = 0; k < 128; k++) {
        const float x = stage[k * 33 + lane];
        const uint64_t xx = pack2(x, x);
        const ulonglong2* w = (const ulonglong2*)(s + k * 64);
        #pragma unroll
        for (int t = 0; t < 16; t++) {
            ulonglong2 wv = w[t];
            fma2(acc2[2 * t + 0], xx, wv.x);
            fma2(acc2[2 * t + 1], xx, wv.y);
        }
    }
    #pragma unroll
    for (int t = 0; t < 32; t++) {
        float a, b; unpack2(acc2[t], a, b);
        m[2 * t + 0] = fmaxf(a, 0.f);
        m[2 * t + 1] = fmaxf(b, 0.f);
    }

    {
        const uint64_t* b2 = (const uint64_t*)(s + 12352);
        #pragma unroll
        for (int t = 0; t < 32; t++) acc2[t] = b2[t];
    }
    #pragma unroll
    for (int k = 0; k < 64; k++) {
        const uint64_t xx = pack2(m[k], m[k]);
        const ulonglong2* w = (const ulonglong2*)(s + 8256 + k * 64);
        #pragma unroll
        for (int t = 0; t < 16; t++) {
            ulonglong2 wv = w[t];
            fma2(acc2[2 * t + 0], xx, wv.x);
            fma2(acc2[2 * t + 1], xx, wv.y);
        }
    }

    if (n < NN) {
        float* op = out_h + (size_t)n * 64;
        #pragma unroll
        for (int t = 0; t < 16; t++) {
            float a, b, c, d;
            unpack2(acc2[2 * t + 0], a, b);
            unpack2(acc2[2 * t + 1], c, d);
            float4 v;
            v.x = stage[(4 * t + 0) * 33 + lane] + a;
            v.y = stage[(4 * t + 1) * 33 + lane] + b;
            v.z = stage[(4 * t + 2) * 33 + lane] + c;
            v.w = stage[(4 * t + 3) * 33 + lane] + d;
            *(float4*)(op + 4 * t) = v;
        }
        const float inv = 1.f / fmaxf(g_cnt[n], 1.f);
        out_c[n * 3 + 0] = g_trans[n * 3 + 0] * inv;
        out_c[n * 3 + 1] = g_trans[n * 3 + 1] * inv;
        out_c[n * 3 + 2] = g_trans[n * 3 + 2] * inv;
    }
}

// ---------------- launch ----------------
extern "C" void kernel_launch(void* const* d_in, const int* in_sizes, int n_in,
                              void* d_out, int out_size)
{
    const float* h     = (const float*)d_in[0];
    const float* coord = (const float*)d_in[1];
    const int*   ei    = (const int*)  d_in[2];
    const float* We1 = (const float*)d_in[3];
    const float* be1 = (const float*)d_in[4];
    const float* We2 = (const float*)d_in[5];
    const float* be2 = (const float*)d_in[6];
    const float* Wn1 = (const float*)d_in[7];
    const float* bn1 = (const float*)d_in[8];
    const float* Wn2 = (const float*)d_in[9];
    const float* bn2 = (const float*)d_in[10];
    const float* Wc1 = (const float*)d_in[11];
    const float* bc1 = (const float*)d_in[12];
    const float* Wc2 = (const float*)d_in[13];

    float* out_h = (float*)d_out;                   // [N, 64]
    float* out_c = (float*)d_out + (size_t)NN * DD; // [N, 3]

    cudaFuncSetAttribute(pq_kernel,   cudaFuncAttributeMaxDynamicSharedMemorySize, PQ_SMEM_BYTES);
    cudaFuncSetAttribute(edge_kernel, cudaFuncAttributeMaxDynamicSharedMemorySize, EDGE_SMEM_BYTES);
    cudaFuncSetAttribute(node_kernel, cudaFuncAttributeMaxDynamicSharedMemorySize, NODE_SMEM_BYTES);

    zero_kernel<<<1024, 256>>>();
    pq_kernel<<<(NN + 255) / 256, 256, PQ_SMEM_BYTES>>>(h, We1, be1);
    edge_kernel<<<296, 128, EDGE_SMEM_BYTES>>>(coord, ei, We1, We2, Wc1, be2, bc1, Wc2);
    node_kernel<<<(NN + 255) / 256, 256, NODE_SMEM_BYTES>>>(h, Wn1, bn1, Wn2, bn2,
                                                            out_h, out_c);
}